// round 1
// baseline (speedup 1.0000x reference)
#include <cuda_runtime.h>

// Problem: pred/target [32,3,512,512] fp32. Loss = sum over 4 Haar subbands of
// mean(|dwt(pred) - dwt(target)|). DWT is linear -> work on diff directly.
//
// Tensor viewed as M = 32*3*256 = 24576 row-PAIRS of 512 floats each.
// Each row = 128 float4. Each thread iteration: one float4 from row 2m and the
// matching float4 from row 2m+1 (for both tensors) -> two 2x2 Haar blocks.

static constexpr int TOTAL_QUADS = 24576 * 128;       // 3,145,728 work items
static constexpr float SCALE = 0.5f / 6291456.0f;     // 0.5 / N_blocks

__global__ void __launch_bounds__(256) dwt_loss_kernel(
    const float4* __restrict__ pred,
    const float4* __restrict__ tgt,
    float* __restrict__ out)
{
    float acc = 0.0f;
    const int stride = gridDim.x * blockDim.x;
    for (int i = blockIdx.x * blockDim.x + threadIdx.x; i < TOTAL_QUADS; i += stride) {
        const int m = i >> 7;            // row-pair index
        const int q = i & 127;           // float4 index within row
        const int base0 = m * 256 + q;   // row 2m   (float4 units)
        const int base1 = base0 + 128;   // row 2m+1

        float4 p0 = pred[base0];
        float4 p1 = pred[base1];
        float4 t0 = tgt[base0];
        float4 t1 = tgt[base1];

        // Block 0: cols 4q, 4q+1
        {
            float a = p0.x - t0.x, b = p0.y - t0.y;
            float c = p1.x - t1.x, d = p1.y - t1.y;
            float apb = a + b, amb = a - b, cpd = c + d, cmd = c - d;
            acc += fabsf(apb + cpd) + fabsf(apb - cpd)
                 + fabsf(amb + cmd) + fabsf(amb - cmd);
        }
        // Block 1: cols 4q+2, 4q+3
        {
            float a = p0.z - t0.z, b = p0.w - t0.w;
            float c = p1.z - t1.z, d = p1.w - t1.w;
            float apb = a + b, amb = a - b, cpd = c + d, cmd = c - d;
            acc += fabsf(apb + cpd) + fabsf(apb - cpd)
                 + fabsf(amb + cmd) + fabsf(amb - cmd);
        }
    }

    // Warp reduction
    #pragma unroll
    for (int o = 16; o > 0; o >>= 1)
        acc += __shfl_xor_sync(0xffffffffu, acc, o);

    __shared__ float warp_sums[8];
    if ((threadIdx.x & 31) == 0)
        warp_sums[threadIdx.x >> 5] = acc;
    __syncthreads();

    if (threadIdx.x < 32) {
        float v = (threadIdx.x < 8) ? warp_sums[threadIdx.x] : 0.0f;
        #pragma unroll
        for (int o = 4; o > 0; o >>= 1)
            v += __shfl_xor_sync(0xffffffffu, v, o);
        if (threadIdx.x == 0)
            atomicAdd(out, v * SCALE);
    }
}

extern "C" void kernel_launch(void* const* d_in, const int* in_sizes, int n_in,
                              void* d_out, int out_size) {
    const float4* pred = (const float4*)d_in[0];
    const float4* tgt  = (const float4*)d_in[1];
    float* out = (float*)d_out;

    // Zero the scalar accumulator (memset node is graph-capturable).
    cudaMemsetAsync(out, 0, sizeof(float), 0);

    // 148 SMs * 16 CTAs of 256 threads -> ~5.2 grid-stride iterations each.
    dwt_loss_kernel<<<2368, 256>>>(pred, tgt, out);
}